// round 14
// baseline (speedup 1.0000x reference)
#include <cuda_runtime.h>
#include <math.h>

#define BB 32
#define CC 64
#define HH 128
#define WW 128
#define HW (HH*WW)
#define CHW (CC*HW)
#define NB 3
#define RH 8

#define TS 32
#define HALO 6
#define TL (TS + 2*HALO)   // 44
#define TLP (TL + 1)       // 45: float2 row stride -> conflict-free LDS.64

#define NRED 2048          // reduce units
#define NUNITS 2112        // reduce + 64 G-map units
#define NTILES 512         // 4x4x32 conv/apply tiles
#define NBLK 288           // persistent blocks (co-resident at 2/SM on 148 SMs)
#define PF 8               // x channels prefetched into registers

// scratch (device globals: no allocation allowed)
__device__ float2 g_am[BB*HW];        // interleaved (avg, max)
__device__ float  g_partA[NRED];
__device__ float  g_partM[NRED];
__device__ float  g_rw[BB*NB];
__device__ float  g_G[3*HW];          // precomputed xg/yg conv response per branch
__device__ unsigned g_cnt = 0;        // router last-block counter (reset in-kernel)
__device__ unsigned g_bar = 0;        // monotonic barrier counter (never reset)

#define DOT2(acc, v, w) \
    acc = fmaf((v).x, (w).x, fmaf((v).y, (w).y, (acc)))

// ---------------------------------------------------------------------------
// Persistent fused kernel: phase 1 = channel reduce + G maps + router;
// spin barrier; phase 2 = conv + sigmoid + apply over 512 tiles.
// ---------------------------------------------------------------------------
__global__ __launch_bounds__(256, 2) void kF(
    const float* __restrict__ x,
    const float* __restrict__ dw0, const float* __restrict__ dw1,
    const float* __restrict__ dw2,
    const float* __restrict__ pw0w, const float* __restrict__ pw0b,
    const float* __restrict__ pw1w, const float* __restrict__ pw1b,
    const float* __restrict__ pw2w, const float* __restrict__ pw2b,
    const float* __restrict__ rw1, const float* __restrict__ rb1,
    const float* __restrict__ rw2, const float* __restrict__ rb2,
    const float* __restrict__ traw,
    float* __restrict__ outY, float* __restrict__ outSA)
{
    // phase-2 shared
    __shared__ float2 s2[TL][TLP];
    __shared__ float2 w0s[9], w1s[49], w2s[49];
    __shared__ float4 saS[TS][9];
    __shared__ float shrw[3];
    __shared__ float shmisc[2];       // bias, invT
    // phase-1 shared
    __shared__ float sA[8], sM[8];
    __shared__ float bA[32], bM[32];
    __shared__ bool amLast;

    const int blk = blockIdx.x;
    const int tid = threadIdx.x;

    // ---- apply-phase thread mapping (used for prefetch + apply) ----
    const int py = tid >> 3;
    const int xq = tid & 7;

    // ---- pre-phase-1 prefetch of FIRST phase-2 tile's PF channels ----
    // (x is an input: independent of phase 1; lands during phase 1)
    const int t0 = blk;               // first tile of this block (blk < 512)
    float4 px[PF];
    {
        int b0 = t0 >> 4, r0 = t0 & 15;
        int xx0 = (r0 & 3) * TS, yy0 = (r0 >> 2) * TS;
        const float* xb0 = x + (size_t)b0 * CHW + (yy0 + py) * WW + xx0 + xq * 4;
        #pragma unroll
        for (int i = 0; i < PF; ++i)
            px[i] = *(const float4*)(xb0 + i * HW);
    }

    // ======================= PHASE 1 =======================
    for (int u = blk; u < NUNITS; u += NBLK) {
        if (u >= NRED) {
            // ---- G-map unit ----
            int p = (u - NRED) * 256 + tid;          // 0..16383
            int gy = p >> 7, gx = p & 127;

            const float* dws[3] = {dw0, dw1, dw2};
            const float* pws[3] = {pw0w, pw1w, pw2w};
            const int ks[3]  = {3, 7, 7};
            const int dil[3] = {1, 1, 2};

            #pragma unroll
            for (int i = 0; i < 3; ++i) {
                int k = ks[i], d = dil[i], r = k / 2;
                float p2 = pws[i][2], p3 = pws[i][3];
                const float* w2 = dws[i] + 2 * k * k;
                const float* w3 = dws[i] + 3 * k * k;
                float acc = 0.0f;
                for (int dy = 0; dy < k; ++dy) {
                    int yy = gy + d * (dy - r);
                    if ((unsigned)yy >= (unsigned)HH) continue;
                    float yv = -1.0f + (float)yy * (2.0f / 127.0f);
                    for (int dx = 0; dx < k; ++dx) {
                        int xx = gx + d * (dx - r);
                        if ((unsigned)xx >= (unsigned)WW) continue;
                        float xv = -1.0f + (float)xx * (2.0f / 127.0f);
                        int t = dy * k + dx;
                        acc += p2 * w2[t] * xv + p3 * w3[t] * yv;
                    }
                }
                g_G[i * HW + p] = acc;
            }
            continue;
        }

        // ---- channel reduce unit: 1 pixel/thread ----
        int b = u >> 6;
        int sp = ((u & 63) << 8) + tid;
        const float* p = x + (size_t)b * CHW + sp;

        float s = 0.0f, m = -INFINITY;
        #pragma unroll 16
        for (int c = 0; c < CC; ++c) {
            float v = p[c * HW];
            s += v;
            m = fmaxf(m, v);
        }
        float av = s * (1.0f / 64.0f);
        g_am[b * HW + sp] = make_float2(av, m);

        float ra = av, rm = m;
        #pragma unroll
        for (int o = 16; o; o >>= 1) {
            ra += __shfl_down_sync(0xffffffffu, ra, o);
            rm += __shfl_down_sync(0xffffffffu, rm, o);
        }
        int w = tid >> 5, l = tid & 31;
        if (l == 0) { sA[w] = ra; sM[w] = rm; }
        __syncthreads();
        if (tid == 0) {
            float ta = 0.f, tm = 0.f;
            #pragma unroll
            for (int i = 0; i < 8; ++i) { ta += sA[i]; tm += sM[i]; }
            g_partA[u] = ta;
            g_partM[u] = tm;
            __threadfence();
            amLast = (atomicAdd(&g_cnt, 1u) == NRED - 1);
        }
        __syncthreads();

        if (amLast) {
            if (tid == 0) g_cnt = 0;   // reset for next replay
            // ---- router (whole block participates) ----
            int batch = tid >> 3;
            int j = tid & 7;
            float a = 0.f, mm = 0.f;
            #pragma unroll
            for (int i = 0; i < 8; ++i) {
                int idx = batch * 64 + j * 8 + i;
                a  += g_partA[idx];
                mm += g_partM[idx];
            }
            #pragma unroll
            for (int o = 4; o; o >>= 1) {
                a  += __shfl_down_sync(0xffffffffu, a,  o, 8);
                mm += __shfl_down_sync(0xffffffffu, mm, o, 8);
            }
            if (j == 0) { bA[batch] = a; bM[batch] = mm; }
            __syncthreads();
            if (tid < 32) {
                float p0 = bA[tid] * (1.0f / (float)HW);
                float p1 = bM[tid] * (1.0f / (float)HW);
                float hid[RH];
                #pragma unroll
                for (int jj = 0; jj < RH; ++jj) {
                    float h = rw1[jj * 4 + 0] * p0 + rw1[jj * 4 + 1] * p1 + rb1[jj];
                    hid[jj] = fmaxf(h, 0.0f);
                }
                float lg[NB];
                float mx = -INFINITY;
                #pragma unroll
                for (int i = 0; i < NB; ++i) {
                    float ss = rb2[i];
                    #pragma unroll
                    for (int jj = 0; jj < RH; ++jj) ss += rw2[i * RH + jj] * hid[jj];
                    lg[i] = ss;
                    mx = fmaxf(mx, ss);
                }
                float den = 0.0f;
                #pragma unroll
                for (int i = 0; i < NB; ++i) { lg[i] = expf(lg[i] - mx); den += lg[i]; }
                float inv = 1.0f / den;
                #pragma unroll
                for (int i = 0; i < NB; ++i) g_rw[tid * NB + i] = lg[i] * inv;
                if (tid == 0) __threadfence();
            }
            __syncthreads();
        }
    }

    // ======================= SPIN BARRIER =======================
    __syncthreads();
    if (tid == 0) {
        __threadfence();
        unsigned a = atomicAdd(&g_bar, 1u);
        unsigned target = (a / NBLK + 1u) * NBLK;
        while (*(volatile unsigned*)&g_bar < target) { }
    }
    __syncthreads();
    __threadfence();   // acquire: make phase-1 writes visible

    // ======================= PHASE 2 =======================
    for (int t = blk; t < NTILES; t += NBLK) {
        const int b  = t >> 4;
        const int rr = t & 15;
        const int x0 = (rr & 3) * TS;
        const int y0 = (rr >> 2) * TS;

        const int base = (y0 + py) * WW + x0 + xq * 4;
        const float* xb = x + (size_t)b * CHW + base;
        float* yb = outY + (size_t)b * CHW + base;

        if (t != t0) {   // first tile's px was prefetched pre-barrier
            #pragma unroll
            for (int i = 0; i < PF; ++i)
                px[i] = *(const float4*)(xb + i * HW);
        }

        if (tid == 0) {
            shrw[0] = g_rw[b * 3 + 0];
            shrw[1] = g_rw[b * 3 + 1];
            shrw[2] = g_rw[b * 3 + 2];
            float T = log1pf(expf(traw[0])) + 1e-6f;
            shmisc[1] = 1.0f / T;
        }
        __syncthreads();
        const float r0 = shrw[0], r1 = shrw[1], r2 = shrw[2];

        if (tid == 0) {
            shmisc[0] = r0 * pw0b[0] + r1 * pw1b[0] + r2 * pw2b[0];
        }
        if (tid < 9) {
            w0s[tid] = make_float2(r0 * pw0w[0] * dw0[0 * 9 + tid],
                                   r0 * pw0w[1] * dw0[1 * 9 + tid]);
        } else if (tid < 58) {
            int i = tid - 9;
            w1s[i] = make_float2(r1 * pw1w[0] * dw1[0 * 49 + i],
                                 r1 * pw1w[1] * dw1[1 * 49 + i]);
        } else if (tid < 107) {
            int i = tid - 58;
            w2s[i] = make_float2(r2 * pw2w[0] * dw2[0 * 49 + i],
                                 r2 * pw2w[1] * dw2[1 * 49 + i]);
        }

        const float2* am = g_am + b * HW;
        for (int i = tid; i < TL * TL; i += 256) {
            int ly = i / TL, lx = i % TL;
            int gy = y0 - HALO + ly, gx = x0 - HALO + lx;
            float2 v = make_float2(0.0f, 0.0f);
            if ((unsigned)gy < (unsigned)HH && (unsigned)gx < (unsigned)WW)
                v = am[gy * WW + gx];
            s2[ly][lx] = v;
        }

        const int oy = tid & 31;
        const int gx8 = tid >> 5;
        const int ox = gx8 * 4;
        const int cy = oy + HALO;
        const int cx = ox + HALO;

        const int pix = (y0 + oy) * WW + x0 + ox;
        float G0[4], G1[4], G2[4];
        #pragma unroll
        for (int j = 0; j < 4; ++j) {
            G0[j] = g_G[0 * HW + pix + j];
            G1[j] = g_G[1 * HW + pix + j];
            G2[j] = g_G[2 * HW + pix + j];
        }

        __syncthreads();

        const float bias = shmisc[0];
        const float invT = shmisc[1];

        float acc0 = bias + r0 * G0[0] + r1 * G1[0] + r2 * G2[0];
        float acc1 = bias + r0 * G0[1] + r1 * G1[1] + r2 * G2[1];
        float acc2 = bias + r0 * G0[2] + r1 * G1[2] + r2 * G2[2];
        float acc3 = bias + r0 * G0[3] + r1 * G1[3] + r2 * G2[3];

        // branch 0: k=3, d=1
        #pragma unroll
        for (int dy = 0; dy < 3; ++dy) {
            const float2* row = s2[cy + dy - 1];
            float2 c[6];
            #pragma unroll
            for (int j = 0; j < 6; ++j) c[j] = row[cx - 1 + j];
            #pragma unroll
            for (int dx = 0; dx < 3; ++dx) {
                float2 w = w0s[dy * 3 + dx];
                DOT2(acc0, c[dx + 0], w);
                DOT2(acc1, c[dx + 1], w);
                DOT2(acc2, c[dx + 2], w);
                DOT2(acc3, c[dx + 3], w);
            }
        }

        // branch 1: k=7, d=1
        #pragma unroll
        for (int dy = 0; dy < 7; ++dy) {
            const float2* row = s2[cy + dy - 3];
            float2 c[10];
            #pragma unroll
            for (int j = 0; j < 10; ++j) c[j] = row[cx - 3 + j];
            #pragma unroll
            for (int dx = 0; dx < 7; ++dx) {
                float2 w = w1s[dy * 7 + dx];
                DOT2(acc0, c[dx + 0], w);
                DOT2(acc1, c[dx + 1], w);
                DOT2(acc2, c[dx + 2], w);
                DOT2(acc3, c[dx + 3], w);
            }
        }

        // branch 2: k=7, d=2
        #pragma unroll
        for (int ty = 0; ty < 7; ++ty) {
            const float2* row = s2[cy + 2 * (ty - 3)];
            {
                float2 c[8];
                #pragma unroll
                for (int j = 0; j < 8; ++j) c[j] = row[cx - 6 + j];
                #pragma unroll
                for (int tx = 0; tx < 3; ++tx) {
                    float2 w = w2s[ty * 7 + tx];
                    DOT2(acc0, c[0 + 2 * tx], w);
                    DOT2(acc1, c[1 + 2 * tx], w);
                    DOT2(acc2, c[2 + 2 * tx], w);
                    DOT2(acc3, c[3 + 2 * tx], w);
                }
            }
            {
                float2 c[10];
                #pragma unroll
                for (int j = 0; j < 10; ++j) c[j] = row[cx + j];
                #pragma unroll
                for (int u2 = 0; u2 < 4; ++u2) {
                    float2 w = w2s[ty * 7 + 3 + u2];
                    DOT2(acc0, c[0 + 2 * u2], w);
                    DOT2(acc1, c[1 + 2 * u2], w);
                    DOT2(acc2, c[2 + 2 * u2], w);
                    DOT2(acc3, c[3 + 2 * u2], w);
                }
            }
        }

        float4 sa;
        sa.x = 1.0f / (1.0f + __expf(-acc0 * invT));
        sa.y = 1.0f / (1.0f + __expf(-acc1 * invT));
        sa.z = 1.0f / (1.0f + __expf(-acc2 * invT));
        sa.w = 1.0f / (1.0f + __expf(-acc3 * invT));
        saS[oy][gx8] = sa;

        __syncthreads();

        float4 sv = saS[py][xq];
        *(float4*)(outSA + b * HW + base) = sv;

        #pragma unroll
        for (int i = 0; i < PF; ++i) {
            float4 v = px[i];
            v.x *= sv.x; v.y *= sv.y; v.z *= sv.z; v.w *= sv.w;
            *(float4*)(yb + i * HW) = v;
        }
        #pragma unroll 14
        for (int c = PF; c < CC; ++c) {
            float4 v = *(const float4*)(xb + c * HW);
            v.x *= sv.x; v.y *= sv.y; v.z *= sv.z; v.w *= sv.w;
            *(float4*)(yb + c * HW) = v;
        }

        __syncthreads();   // protect smem reuse across tile iterations
    }
}

// ---------------------------------------------------------------------------
extern "C" void kernel_launch(void* const* d_in, const int* in_sizes, int n_in,
                              void* d_out, int out_size) {
    const float* x    = (const float*)d_in[0];
    const float* dw0  = (const float*)d_in[1];
    const float* dw1  = (const float*)d_in[2];
    const float* dw2  = (const float*)d_in[3];
    const float* pw0w = (const float*)d_in[4];
    const float* pw0b = (const float*)d_in[5];
    const float* pw1w = (const float*)d_in[6];
    const float* pw1b = (const float*)d_in[7];
    const float* pw2w = (const float*)d_in[8];
    const float* pw2b = (const float*)d_in[9];
    const float* rw1  = (const float*)d_in[10];
    const float* rb1  = (const float*)d_in[11];
    const float* rw2  = (const float*)d_in[12];
    const float* rb2  = (const float*)d_in[13];
    const float* traw = (const float*)d_in[14];

    float* outY  = (float*)d_out;
    float* outSA = (float*)d_out + (size_t)BB * CHW;

    kF<<<NBLK, 256>>>(x, dw0, dw1, dw2, pw0w, pw0b, pw1w, pw1b, pw2w, pw2b,
                      rw1, rb1, rw2, rb2, traw, outY, outSA);
}

// round 15
// speedup vs baseline: 1.1238x; 1.1238x over previous
#include <cuda_runtime.h>
#include <math.h>

#define BB 32
#define CC 64
#define HH 128
#define WW 128
#define HW (HH*WW)
#define CHW (CC*HW)
#define NB 3
#define RH 8

#define TSX 32             // tile width
#define TSY 16             // tile height
#define HALO 6
#define TLX (TSX + 2*HALO) // 44
#define TLY (TSY + 2*HALO) // 28
#define TLP (TLX + 1)      // 45 float2 row stride -> conflict-free LDS.64

#define NRED 2048          // reduce blocks in kA
#define PF 4               // x channels prefetched into registers during conv

// scratch (device globals: no allocation allowed)
__device__ float2 g_am[BB*HW];        // interleaved (avg, max)
__device__ float  g_partA[NRED];
__device__ float  g_partM[NRED];
__device__ float  g_rw[BB*NB];
__device__ float  g_G[3*HW];          // precomputed xg/yg conv response per branch
__device__ unsigned g_cnt = 0;        // last-block counter (reset in-kernel)

// ---------------------------------------------------------------------------
// Kernel A: blocks 0..2047: per-pixel channel reduce (avg, max), 1 px/thread.
// Blocks 2048..2111: G maps. The LAST reduce block (threadfence+atomic) also
// computes the router MLP — deterministic (reduces fully-written partials).
// ---------------------------------------------------------------------------
__global__ __launch_bounds__(256) void kA(
    const float* __restrict__ x,
    const float* __restrict__ dw0, const float* __restrict__ dw1,
    const float* __restrict__ dw2,
    const float* __restrict__ pw0w, const float* __restrict__ pw1w,
    const float* __restrict__ pw2w,
    const float* __restrict__ rw1, const float* __restrict__ rb1,
    const float* __restrict__ rw2, const float* __restrict__ rb2)
{
    int blk = blockIdx.x;
    int tid = threadIdx.x;

    if (blk >= NRED) {
        // ---- G-map computation (data-independent xg/yg conv response) ----
        int p = (blk - NRED) * 256 + tid;            // 0..16383
        int gy = p >> 7, gx = p & 127;

        const float* dws[3] = {dw0, dw1, dw2};
        const float* pws[3] = {pw0w, pw1w, pw2w};
        const int ks[3]  = {3, 7, 7};
        const int dil[3] = {1, 1, 2};

        #pragma unroll
        for (int i = 0; i < 3; ++i) {
            int k = ks[i], d = dil[i], r = k / 2;
            float p2 = pws[i][2], p3 = pws[i][3];
            const float* w2 = dws[i] + 2 * k * k;
            const float* w3 = dws[i] + 3 * k * k;
            float acc = 0.0f;
            for (int dy = 0; dy < k; ++dy) {
                int yy = gy + d * (dy - r);
                if ((unsigned)yy >= (unsigned)HH) continue;
                float yv = -1.0f + (float)yy * (2.0f / 127.0f);
                for (int dx = 0; dx < k; ++dx) {
                    int xx = gx + d * (dx - r);
                    if ((unsigned)xx >= (unsigned)WW) continue;
                    float xv = -1.0f + (float)xx * (2.0f / 127.0f);
                    int t = dy * k + dx;
                    acc += p2 * w2[t] * xv + p3 * w3[t] * yv;
                }
            }
            g_G[i * HW + p] = acc;
        }
        return;
    }

    // ---- channel reduce: 1 pixel/thread, scalar coalesced loads ----
    int b = blk >> 6;
    int sp = ((blk & 63) << 8) + tid;
    const float* p = x + (size_t)b * CHW + sp;

    float s = 0.0f, m = -INFINITY;
    #pragma unroll 16
    for (int c = 0; c < CC; ++c) {
        float v = p[c * HW];
        s += v;
        m = fmaxf(m, v);
    }
    float av = s * (1.0f / 64.0f);
    g_am[b * HW + sp] = make_float2(av, m);

    // deterministic block reduction of (sum of avg, sum of max)
    float ra = av, rm = m;
    #pragma unroll
    for (int o = 16; o; o >>= 1) {
        ra += __shfl_down_sync(0xffffffffu, ra, o);
        rm += __shfl_down_sync(0xffffffffu, rm, o);
    }
    __shared__ float sA[8], sM[8];
    int w = tid >> 5, l = tid & 31;
    if (l == 0) { sA[w] = ra; sM[w] = rm; }
    __syncthreads();

    __shared__ bool amLast;
    if (tid == 0) {
        float ta = 0.f, tm = 0.f;
        #pragma unroll
        for (int i = 0; i < 8; ++i) { ta += sA[i]; tm += sM[i]; }
        g_partA[blk] = ta;
        g_partM[blk] = tm;
        __threadfence();
        amLast = (atomicAdd(&g_cnt, 1u) == NRED - 1);
    }
    __syncthreads();
    if (!amLast) return;

    if (tid == 0) g_cnt = 0;   // reset for next graph replay

    // ---- router (former kB), by the designated last block ----
    int batch = tid >> 3;
    int j = tid & 7;
    float a = 0.f, mm = 0.f;
    #pragma unroll
    for (int i = 0; i < 8; ++i) {
        int idx = batch * 64 + j * 8 + i;
        a  += g_partA[idx];
        mm += g_partM[idx];
    }
    #pragma unroll
    for (int o = 4; o; o >>= 1) {
        a  += __shfl_down_sync(0xffffffffu, a,  o, 8);
        mm += __shfl_down_sync(0xffffffffu, mm, o, 8);
    }
    __shared__ float bA[32], bM[32];
    if (j == 0) { bA[batch] = a; bM[batch] = mm; }
    __syncthreads();

    if (tid < 32) {
        float p0 = bA[tid] * (1.0f / (float)HW);
        float p1 = bM[tid] * (1.0f / (float)HW);
        // pooled xg, yg are exactly 0 (symmetric linspace)
        float hid[RH];
        #pragma unroll
        for (int jj = 0; jj < RH; ++jj) {
            float h = rw1[jj * 4 + 0] * p0 + rw1[jj * 4 + 1] * p1 + rb1[jj];
            hid[jj] = fmaxf(h, 0.0f);
        }
        float lg[NB];
        float mx = -INFINITY;
        #pragma unroll
        for (int i = 0; i < NB; ++i) {
            float ss = rb2[i];
            #pragma unroll
            for (int jj = 0; jj < RH; ++jj) ss += rw2[i * RH + jj] * hid[jj];
            lg[i] = ss;
            mx = fmaxf(mx, ss);
        }
        float den = 0.0f;
        #pragma unroll
        for (int i = 0; i < NB; ++i) { lg[i] = expf(lg[i] - mx); den += lg[i]; }
        float inv = 1.0f / den;
        #pragma unroll
        for (int i = 0; i < NB; ++i) g_rw[tid * NB + i] = lg[i] * inv;
    }
}

// ---------------------------------------------------------------------------
// Kernel C: 32x16 tile, 2 outputs/thread, 4 blocks/SM (32 warps for apply BW).
// grid (4, 8, 32) = 1024 blocks -> finer wave mixing of conv/apply phases.
// ---------------------------------------------------------------------------
#define DOT2(acc, v, w) \
    acc = fmaf((v).x, (w).x, fmaf((v).y, (w).y, (acc)))

__global__ __launch_bounds__(256, 4) void kC(
    const float* __restrict__ x,
    const float* __restrict__ dw0, const float* __restrict__ dw1, const float* __restrict__ dw2,
    const float* __restrict__ pw0w, const float* __restrict__ pw0b,
    const float* __restrict__ pw1w, const float* __restrict__ pw1b,
    const float* __restrict__ pw2w, const float* __restrict__ pw2b,
    const float* __restrict__ traw,
    float* __restrict__ outY, float* __restrict__ outSA)
{
    __shared__ float2 s2[TLY][TLP];
    __shared__ float2 w0s[9], w1s[49], w2s[49];
    __shared__ float2 saS[TSY][17];   // [16 rows][16 pairs + pad]
    __shared__ float shrw[3];
    __shared__ float shmisc[2];       // bias, invT

    const int b  = blockIdx.z;
    const int x0 = blockIdx.x * TSX;
    const int y0 = blockIdx.y * TSY;
    const int tid = threadIdx.x;

    // apply-phase mapping: thread -> 2 consecutive px
    const int py = tid >> 4;          // 0..15 (row)
    const int xp = tid & 15;          // 0..15 (pair)
    const int base = (y0 + py) * WW + x0 + xp * 2;
    const float* xb = x + (size_t)b * CHW + base;
    float* yb = outY + (size_t)b * CHW + base;

    // register prefetch: first PF channels of x (lands during conv)
    float2 px[PF];
    #pragma unroll
    for (int i = 0; i < PF; ++i)
        px[i] = *(const float2*)(xb + i * HW);

    if (tid == 0) {
        shrw[0] = g_rw[b * 3 + 0];
        shrw[1] = g_rw[b * 3 + 1];
        shrw[2] = g_rw[b * 3 + 2];
        float T = log1pf(expf(traw[0])) + 1e-6f;
        shmisc[1] = 1.0f / T;
    }
    __syncthreads();
    const float r0 = shrw[0], r1 = shrw[1], r2 = shrw[2];

    if (tid == 0) {
        shmisc[0] = r0 * pw0b[0] + r1 * pw1b[0] + r2 * pw2b[0];
    }
    // fold router weight * pointwise weight into depthwise taps (ch0=avg, ch1=max)
    if (tid < 9) {
        w0s[tid] = make_float2(r0 * pw0w[0] * dw0[0 * 9 + tid],
                               r0 * pw0w[1] * dw0[1 * 9 + tid]);
    } else if (tid < 58) {
        int i = tid - 9;
        w1s[i] = make_float2(r1 * pw1w[0] * dw1[0 * 49 + i],
                             r1 * pw1w[1] * dw1[1 * 49 + i]);
    } else if (tid < 107) {
        int i = tid - 58;
        w2s[i] = make_float2(r2 * pw2w[0] * dw2[0 * 49 + i],
                             r2 * pw2w[1] * dw2[1 * 49 + i]);
    }

    // load (avg,max) tile with zero halo padding (28x44)
    const float2* am = g_am + b * HW;
    for (int i = tid; i < TLY * TLX; i += 256) {
        int ly = i / TLX, lx = i % TLX;
        int gy = y0 - HALO + ly, gx = x0 - HALO + lx;
        float2 v = make_float2(0.0f, 0.0f);
        if ((unsigned)gy < (unsigned)HH && (unsigned)gx < (unsigned)WW)
            v = am[gy * WW + gx];
        s2[ly][lx] = v;
    }

    // conv mapping: lane -> row (conflict-free), 16 x-pairs
    const int oy = tid & 15;          // 0..15 (row)
    const int gx8 = tid >> 4;         // 0..15 (x pair)
    const int ox = gx8 * 2;
    const int cy = oy + HALO;
    const int cx = ox + HALO;

    // G map contribution (global loads, L2-resident) — issue before barrier
    const int pix = (y0 + oy) * WW + x0 + ox;
    float G0[2], G1[2], G2[2];
    #pragma unroll
    for (int j = 0; j < 2; ++j) {
        G0[j] = g_G[0 * HW + pix + j];
        G1[j] = g_G[1 * HW + pix + j];
        G2[j] = g_G[2 * HW + pix + j];
    }

    __syncthreads();

    const float bias = shmisc[0];
    const float invT = shmisc[1];

    float acc0 = bias + r0 * G0[0] + r1 * G1[0] + r2 * G2[0];
    float acc1 = bias + r0 * G0[1] + r1 * G1[1] + r2 * G2[1];

    // branch 0: k=3, d=1
    #pragma unroll
    for (int dy = 0; dy < 3; ++dy) {
        const float2* row = s2[cy + dy - 1];
        float2 c[4];
        #pragma unroll
        for (int j = 0; j < 4; ++j) c[j] = row[cx - 1 + j];
        #pragma unroll
        for (int dx = 0; dx < 3; ++dx) {
            float2 w = w0s[dy * 3 + dx];
            DOT2(acc0, c[dx + 0], w);
            DOT2(acc1, c[dx + 1], w);
        }
    }

    // branch 1: k=7, d=1
    #pragma unroll
    for (int dy = 0; dy < 7; ++dy) {
        const float2* row = s2[cy + dy - 3];
        float2 c[8];
        #pragma unroll
        for (int j = 0; j < 8; ++j) c[j] = row[cx - 3 + j];
        #pragma unroll
        for (int dx = 0; dx < 7; ++dx) {
            float2 w = w1s[dy * 7 + dx];
            DOT2(acc0, c[dx + 0], w);
            DOT2(acc1, c[dx + 1], w);
        }
    }

    // branch 2: k=7, d=2
    #pragma unroll
    for (int ty = 0; ty < 7; ++ty) {
        const float2* row = s2[cy + 2 * (ty - 3)];
        float2 c[14];
        #pragma unroll
        for (int j = 0; j < 14; ++j) c[j] = row[cx - 6 + j];
        #pragma unroll
        for (int tx = 0; tx < 7; ++tx) {
            float2 w = w2s[ty * 7 + tx];
            DOT2(acc0, c[2 * tx + 0], w);
            DOT2(acc1, c[2 * tx + 1], w);
        }
    }

    float2 sa;
    sa.x = 1.0f / (1.0f + __expf(-acc0 * invT));
    sa.y = 1.0f / (1.0f + __expf(-acc1 * invT));
    saS[oy][gx8] = sa;

    __syncthreads();

    // apply phase
    float2 sv = saS[py][xp];
    *(float2*)(outSA + b * HW + base) = sv;

    #pragma unroll
    for (int i = 0; i < PF; ++i) {
        float2 v = px[i];
        v.x *= sv.x; v.y *= sv.y;
        *(float2*)(yb + i * HW) = v;
    }
    #pragma unroll 15
    for (int c = PF; c < CC; ++c) {
        float2 v = *(const float2*)(xb + c * HW);
        v.x *= sv.x; v.y *= sv.y;
        *(float2*)(yb + c * HW) = v;
    }
}

// ---------------------------------------------------------------------------
extern "C" void kernel_launch(void* const* d_in, const int* in_sizes, int n_in,
                              void* d_out, int out_size) {
    const float* x    = (const float*)d_in[0];
    const float* dw0  = (const float*)d_in[1];
    const float* dw1  = (const float*)d_in[2];
    const float* dw2  = (const float*)d_in[3];
    const float* pw0w = (const float*)d_in[4];
    const float* pw0b = (const float*)d_in[5];
    const float* pw1w = (const float*)d_in[6];
    const float* pw1b = (const float*)d_in[7];
    const float* pw2w = (const float*)d_in[8];
    const float* pw2b = (const float*)d_in[9];
    const float* rw1  = (const float*)d_in[10];
    const float* rb1  = (const float*)d_in[11];
    const float* rw2  = (const float*)d_in[12];
    const float* rb2  = (const float*)d_in[13];
    const float* traw = (const float*)d_in[14];

    float* outY  = (float*)d_out;
    float* outSA = (float*)d_out + (size_t)BB * CHW;

    kA<<<NRED + 64, 256>>>(x, dw0, dw1, dw2, pw0w, pw1w, pw2w,
                           rw1, rb1, rw2, rb2);
    dim3 gc(WW / TSX, HH / TSY, BB);
    kC<<<gc, 256>>>(x, dw0, dw1, dw2, pw0w, pw0b, pw1w, pw1b, pw2w, pw2b,
                    traw, outY, outSA);
}

// round 16
// speedup vs baseline: 1.1242x; 1.0004x over previous
#include <cuda_runtime.h>
#include <math.h>

#define BB 32
#define CC 64
#define HH 128
#define WW 128
#define HW (HH*WW)
#define CHW (CC*HW)
#define NB 3
#define RH 8

#define TSX 32             // tile width
#define TSY 16             // tile height
#define HALO 6
#define TLX (TSX + 2*HALO) // 44
#define TLY (TSY + 2*HALO) // 28
#define TLP (TLX + 1)      // 45 float2 row stride -> conflict-free LDS.64

#define NRED 2048          // reduce blocks in kA
#define PF 4               // x channels prefetched into registers during conv
#define GRP 6              // apply-phase channel burst size (loads then stores)

// scratch (device globals: no allocation allowed)
__device__ float2 g_am[BB*HW];        // interleaved (avg, max)
__device__ float  g_partA[NRED];
__device__ float  g_partM[NRED];
__device__ float  g_rw[BB*NB];
__device__ float  g_G[3*HW];          // precomputed xg/yg conv response per branch
__device__ unsigned g_cnt = 0;        // last-block counter (reset in-kernel)

__device__ __forceinline__ void stg_cs2(float* p, float2 v) {
    asm volatile("st.global.cs.v2.f32 [%0], {%1,%2};"
                 :: "l"(p), "f"(v.x), "f"(v.y) : "memory");
}

// ---------------------------------------------------------------------------
// Kernel A: blocks 0..2047: per-pixel channel reduce (avg, max), 1 px/thread.
// Blocks 2048..2111: G maps. The LAST reduce block (threadfence+atomic) also
// computes the router MLP — deterministic (reduces fully-written partials).
// ---------------------------------------------------------------------------
__global__ __launch_bounds__(256) void kA(
    const float* __restrict__ x,
    const float* __restrict__ dw0, const float* __restrict__ dw1,
    const float* __restrict__ dw2,
    const float* __restrict__ pw0w, const float* __restrict__ pw1w,
    const float* __restrict__ pw2w,
    const float* __restrict__ rw1, const float* __restrict__ rb1,
    const float* __restrict__ rw2, const float* __restrict__ rb2)
{
    int blk = blockIdx.x;
    int tid = threadIdx.x;

    if (blk >= NRED) {
        // ---- G-map computation (data-independent xg/yg conv response) ----
        int p = (blk - NRED) * 256 + tid;            // 0..16383
        int gy = p >> 7, gx = p & 127;

        const float* dws[3] = {dw0, dw1, dw2};
        const float* pws[3] = {pw0w, pw1w, pw2w};
        const int ks[3]  = {3, 7, 7};
        const int dil[3] = {1, 1, 2};

        #pragma unroll
        for (int i = 0; i < 3; ++i) {
            int k = ks[i], d = dil[i], r = k / 2;
            float p2 = pws[i][2], p3 = pws[i][3];
            const float* w2 = dws[i] + 2 * k * k;
            const float* w3 = dws[i] + 3 * k * k;
            float acc = 0.0f;
            for (int dy = 0; dy < k; ++dy) {
                int yy = gy + d * (dy - r);
                if ((unsigned)yy >= (unsigned)HH) continue;
                float yv = -1.0f + (float)yy * (2.0f / 127.0f);
                for (int dx = 0; dx < k; ++dx) {
                    int xx = gx + d * (dx - r);
                    if ((unsigned)xx >= (unsigned)WW) continue;
                    float xv = -1.0f + (float)xx * (2.0f / 127.0f);
                    int t = dy * k + dx;
                    acc += p2 * w2[t] * xv + p3 * w3[t] * yv;
                }
            }
            g_G[i * HW + p] = acc;
        }
        return;
    }

    // ---- channel reduce: 1 pixel/thread, scalar coalesced loads ----
    int b = blk >> 6;
    int sp = ((blk & 63) << 8) + tid;
    const float* p = x + (size_t)b * CHW + sp;

    float s = 0.0f, m = -INFINITY;
    #pragma unroll 16
    for (int c = 0; c < CC; ++c) {
        float v = p[c * HW];
        s += v;
        m = fmaxf(m, v);
    }
    float av = s * (1.0f / 64.0f);
    g_am[b * HW + sp] = make_float2(av, m);

    // deterministic block reduction of (sum of avg, sum of max)
    float ra = av, rm = m;
    #pragma unroll
    for (int o = 16; o; o >>= 1) {
        ra += __shfl_down_sync(0xffffffffu, ra, o);
        rm += __shfl_down_sync(0xffffffffu, rm, o);
    }
    __shared__ float sA[8], sM[8];
    int w = tid >> 5, l = tid & 31;
    if (l == 0) { sA[w] = ra; sM[w] = rm; }
    __syncthreads();

    __shared__ bool amLast;
    if (tid == 0) {
        float ta = 0.f, tm = 0.f;
        #pragma unroll
        for (int i = 0; i < 8; ++i) { ta += sA[i]; tm += sM[i]; }
        g_partA[blk] = ta;
        g_partM[blk] = tm;
        __threadfence();
        amLast = (atomicAdd(&g_cnt, 1u) == NRED - 1);
    }
    __syncthreads();
    if (!amLast) return;

    if (tid == 0) g_cnt = 0;   // reset for next graph replay

    // ---- router (former kB), by the designated last block ----
    int batch = tid >> 3;
    int j = tid & 7;
    float a = 0.f, mm = 0.f;
    #pragma unroll
    for (int i = 0; i < 8; ++i) {
        int idx = batch * 64 + j * 8 + i;
        a  += g_partA[idx];
        mm += g_partM[idx];
    }
    #pragma unroll
    for (int o = 4; o; o >>= 1) {
        a  += __shfl_down_sync(0xffffffffu, a,  o, 8);
        mm += __shfl_down_sync(0xffffffffu, mm, o, 8);
    }
    __shared__ float bA[32], bM[32];
    if (j == 0) { bA[batch] = a; bM[batch] = mm; }
    __syncthreads();

    if (tid < 32) {
        float p0 = bA[tid] * (1.0f / (float)HW);
        float p1 = bM[tid] * (1.0f / (float)HW);
        // pooled xg, yg are exactly 0 (symmetric linspace)
        float hid[RH];
        #pragma unroll
        for (int jj = 0; jj < RH; ++jj) {
            float h = rw1[jj * 4 + 0] * p0 + rw1[jj * 4 + 1] * p1 + rb1[jj];
            hid[jj] = fmaxf(h, 0.0f);
        }
        float lg[NB];
        float mx = -INFINITY;
        #pragma unroll
        for (int i = 0; i < NB; ++i) {
            float ss = rb2[i];
            #pragma unroll
            for (int jj = 0; jj < RH; ++jj) ss += rw2[i * RH + jj] * hid[jj];
            lg[i] = ss;
            mx = fmaxf(mx, ss);
        }
        float den = 0.0f;
        #pragma unroll
        for (int i = 0; i < NB; ++i) { lg[i] = expf(lg[i] - mx); den += lg[i]; }
        float inv = 1.0f / den;
        #pragma unroll
        for (int i = 0; i < NB; ++i) g_rw[tid * NB + i] = lg[i] * inv;
    }
}

// ---------------------------------------------------------------------------
// Kernel C: 32x16 tile, 2 outputs/thread, 4 blocks/SM. Apply phase groups
// channels into GRP-sized bursts (loads then stores) to cut DRAM R/W
// turnaround; Y stores use st.global.cs (write-once, evict-first).
// ---------------------------------------------------------------------------
#define DOT2(acc, v, w) \
    acc = fmaf((v).x, (w).x, fmaf((v).y, (w).y, (acc)))

__global__ __launch_bounds__(256, 4) void kC(
    const float* __restrict__ x,
    const float* __restrict__ dw0, const float* __restrict__ dw1, const float* __restrict__ dw2,
    const float* __restrict__ pw0w, const float* __restrict__ pw0b,
    const float* __restrict__ pw1w, const float* __restrict__ pw1b,
    const float* __restrict__ pw2w, const float* __restrict__ pw2b,
    const float* __restrict__ traw,
    float* __restrict__ outY, float* __restrict__ outSA)
{
    __shared__ float2 s2[TLY][TLP];
    __shared__ float2 w0s[9], w1s[49], w2s[49];
    __shared__ float2 saS[TSY][17];   // [16 rows][16 pairs + pad]
    __shared__ float shrw[3];
    __shared__ float shmisc[2];       // bias, invT

    const int b  = blockIdx.z;
    const int x0 = blockIdx.x * TSX;
    const int y0 = blockIdx.y * TSY;
    const int tid = threadIdx.x;

    // apply-phase mapping: thread -> 2 consecutive px
    const int py = tid >> 4;          // 0..15 (row)
    const int xp = tid & 15;          // 0..15 (pair)
    const int base = (y0 + py) * WW + x0 + xp * 2;
    const float* xb = x + (size_t)b * CHW + base;
    float* yb = outY + (size_t)b * CHW + base;

    // register prefetch: first PF channels of x (lands during conv)
    float2 px[PF];
    #pragma unroll
    for (int i = 0; i < PF; ++i)
        px[i] = *(const float2*)(xb + i * HW);

    if (tid == 0) {
        shrw[0] = g_rw[b * 3 + 0];
        shrw[1] = g_rw[b * 3 + 1];
        shrw[2] = g_rw[b * 3 + 2];
        float T = log1pf(expf(traw[0])) + 1e-6f;
        shmisc[1] = 1.0f / T;
    }
    __syncthreads();
    const float r0 = shrw[0], r1 = shrw[1], r2 = shrw[2];

    if (tid == 0) {
        shmisc[0] = r0 * pw0b[0] + r1 * pw1b[0] + r2 * pw2b[0];
    }
    // fold router weight * pointwise weight into depthwise taps (ch0=avg, ch1=max)
    if (tid < 9) {
        w0s[tid] = make_float2(r0 * pw0w[0] * dw0[0 * 9 + tid],
                               r0 * pw0w[1] * dw0[1 * 9 + tid]);
    } else if (tid < 58) {
        int i = tid - 9;
        w1s[i] = make_float2(r1 * pw1w[0] * dw1[0 * 49 + i],
                             r1 * pw1w[1] * dw1[1 * 49 + i]);
    } else if (tid < 107) {
        int i = tid - 58;
        w2s[i] = make_float2(r2 * pw2w[0] * dw2[0 * 49 + i],
                             r2 * pw2w[1] * dw2[1 * 49 + i]);
    }

    // load (avg,max) tile with zero halo padding (28x44)
    const float2* am = g_am + b * HW;
    for (int i = tid; i < TLY * TLX; i += 256) {
        int ly = i / TLX, lx = i % TLX;
        int gy = y0 - HALO + ly, gx = x0 - HALO + lx;
        float2 v = make_float2(0.0f, 0.0f);
        if ((unsigned)gy < (unsigned)HH && (unsigned)gx < (unsigned)WW)
            v = am[gy * WW + gx];
        s2[ly][lx] = v;
    }

    // conv mapping: lane -> row (conflict-free), 16 x-pairs
    const int oy = tid & 15;          // 0..15 (row)
    const int gx8 = tid >> 4;         // 0..15 (x pair)
    const int ox = gx8 * 2;
    const int cy = oy + HALO;
    const int cx = ox + HALO;

    // G map contribution (global loads, L2-resident) — issue before barrier
    const int pix = (y0 + oy) * WW + x0 + ox;
    float G0[2], G1[2], G2[2];
    #pragma unroll
    for (int j = 0; j < 2; ++j) {
        G0[j] = g_G[0 * HW + pix + j];
        G1[j] = g_G[1 * HW + pix + j];
        G2[j] = g_G[2 * HW + pix + j];
    }

    __syncthreads();

    const float bias = shmisc[0];
    const float invT = shmisc[1];

    float acc0 = bias + r0 * G0[0] + r1 * G1[0] + r2 * G2[0];
    float acc1 = bias + r0 * G0[1] + r1 * G1[1] + r2 * G2[1];

    // branch 0: k=3, d=1
    #pragma unroll
    for (int dy = 0; dy < 3; ++dy) {
        const float2* row = s2[cy + dy - 1];
        float2 c[4];
        #pragma unroll
        for (int j = 0; j < 4; ++j) c[j] = row[cx - 1 + j];
        #pragma unroll
        for (int dx = 0; dx < 3; ++dx) {
            float2 w = w0s[dy * 3 + dx];
            DOT2(acc0, c[dx + 0], w);
            DOT2(acc1, c[dx + 1], w);
        }
    }

    // branch 1: k=7, d=1
    #pragma unroll
    for (int dy = 0; dy < 7; ++dy) {
        const float2* row = s2[cy + dy - 3];
        float2 c[8];
        #pragma unroll
        for (int j = 0; j < 8; ++j) c[j] = row[cx - 3 + j];
        #pragma unroll
        for (int dx = 0; dx < 7; ++dx) {
            float2 w = w1s[dy * 7 + dx];
            DOT2(acc0, c[dx + 0], w);
            DOT2(acc1, c[dx + 1], w);
        }
    }

    // branch 2: k=7, d=2
    #pragma unroll
    for (int ty = 0; ty < 7; ++ty) {
        const float2* row = s2[cy + 2 * (ty - 3)];
        float2 c[14];
        #pragma unroll
        for (int j = 0; j < 14; ++j) c[j] = row[cx - 6 + j];
        #pragma unroll
        for (int tx = 0; tx < 7; ++tx) {
            float2 w = w2s[ty * 7 + tx];
            DOT2(acc0, c[2 * tx + 0], w);
            DOT2(acc1, c[2 * tx + 1], w);
        }
    }

    float2 sa;
    sa.x = 1.0f / (1.0f + __expf(-acc0 * invT));
    sa.y = 1.0f / (1.0f + __expf(-acc1 * invT));
    saS[oy][gx8] = sa;

    __syncthreads();

    // apply phase
    float2 sv = saS[py][xp];
    *(float2*)(outSA + b * HW + base) = sv;

    #pragma unroll
    for (int i = 0; i < PF; ++i) {
        float2 v = px[i];
        v.x *= sv.x; v.y *= sv.y;
        stg_cs2(yb + i * HW, v);
    }

    // burst-grouped apply: GRP loads then GRP stores per group
    #pragma unroll
    for (int g = 0; g < (CC - PF) / GRP; ++g) {
        const int c0 = PF + g * GRP;
        float2 v[GRP];
        #pragma unroll
        for (int k = 0; k < GRP; ++k)
            v[k] = *(const float2*)(xb + (c0 + k) * HW);
        #pragma unroll
        for (int k = 0; k < GRP; ++k) {
            v[k].x *= sv.x; v[k].y *= sv.y;
            stg_cs2(yb + (c0 + k) * HW, v[k]);
        }
    }
}

// ---------------------------------------------------------------------------
extern "C" void kernel_launch(void* const* d_in, const int* in_sizes, int n_in,
                              void* d_out, int out_size) {
    const float* x    = (const float*)d_in[0];
    const float* dw0  = (const float*)d_in[1];
    const float* dw1  = (const float*)d_in[2];
    const float* dw2  = (const float*)d_in[3];
    const float* pw0w = (const float*)d_in[4];
    const float* pw0b = (const float*)d_in[5];
    const float* pw1w = (const float*)d_in[6];
    const float* pw1b = (const float*)d_in[7];
    const float* pw2w = (const float*)d_in[8];
    const float* pw2b = (const float*)d_in[9];
    const float* rw1  = (const float*)d_in[10];
    const float* rb1  = (const float*)d_in[11];
    const float* rw2  = (const float*)d_in[12];
    const float* rb2  = (const float*)d_in[13];
    const float* traw = (const float*)d_in[14];

    float* outY  = (float*)d_out;
    float* outSA = (float*)d_out + (size_t)BB * CHW;

    kA<<<NRED + 64, 256>>>(x, dw0, dw1, dw2, pw0w, pw1w, pw2w,
                           rw1, rb1, rw2, rb2);
    dim3 gc(WW / TSX, HH / TSY, BB);
    kC<<<gc, 256>>>(x, dw0, dw1, dw2, pw0w, pw0b, pw1w, pw1b, pw2w, pw2b,
                    traw, outY, outSA);
}